// round 13
// baseline (speedup 1.0000x reference)
#include <cuda_runtime.h>
#include <cuda_fp16.h>

#define T_  256
#define B_  64
#define H_  1024
#define G3  3072
#define I_  2048
#define TB  16384   // T_*B_

#define NSLOT      8
// smem words: Ws[48*512] | Hb[8][2048] | red[3072] | mbar[32]
#define WS_WORDS   (48 * 512)                // W: 96KB fp16
#define HB_SLOT_W  2048                      // one 64x64 fp16 chunk (8KB)
#define RED_OFF    (WS_WORDS + NSLOT * HB_SLOT_W)
#define RED_WORDS  3072
#define MBAR_W     (RED_OFF + RED_WORDS)
#define SMEM_STEP  ((MBAR_W + 32) * 4)       // ~173KB (1 CTA/SM)

// ---------------- scratch ----------------------------------------------------
__device__ float g_gi[2][(size_t)TB * G3];
__device__ float g_buf[2][(size_t)TB * I_];
// h: fp16 pairs; per (parity,dir): 16 chunks x 2048 words; chunk = 64 rows x
// 32 words; word(b,kw) = (kw>>5)*2048 + b*32 + ((kw&31) ^ ((b&7)<<2))
__device__ __align__(1024) unsigned g_htf[2][2][B_ * H_ / 2];
__device__ unsigned g_cflag[2][16];          // per-(dir,chunk) producer counts
__device__ unsigned g_done[2];               // per-dir completed-read counter

// ---------------- helpers ---------------------------------------------------
__device__ __forceinline__ unsigned f2h2(float lo, float hi) {
    unsigned u;                              // pack: lower=lo, upper=hi
    asm("cvt.rn.f16x2.f32 %0, %1, %2;" : "=r"(u) : "f"(hi), "f"(lo));
    return u;
}
__device__ __forceinline__ void mmah(float* c, const unsigned* a, const unsigned* b) {
    asm volatile(
        "mma.sync.aligned.m16n8k16.row.col.f32.f16.f16.f32 "
        "{%0,%1,%2,%3}, {%4,%5,%6,%7}, {%8,%9}, {%0,%1,%2,%3};"
        : "+f"(c[0]), "+f"(c[1]), "+f"(c[2]), "+f"(c[3])
        : "r"(a[0]), "r"(a[1]), "r"(a[2]), "r"(a[3]), "r"(b[0]), "r"(b[1]));
}
__device__ __forceinline__ void mbar_wait(unsigned mb, unsigned par) {
    asm volatile(
        "{\n\t.reg .pred P;\nW_%=:\n\t"
        "mbarrier.try_wait.parity.shared::cta.b64 P, [%0], %1;\n\t"
        "@!P bra W_%=;\n\t}" :: "r"(mb), "r"(par) : "memory");
}
__device__ __forceinline__ unsigned ldacq(const unsigned* p) {
    unsigned v;
    asm volatile("ld.acquire.gpu.global.u32 %0, [%1];" : "=r"(v) : "l"(p) : "memory");
    return v;
}
__device__ __forceinline__ void red_release(unsigned* p) {
    asm volatile("red.release.gpu.global.add.u32 [%0], %1;"
                 :: "l"(p), "r"(1u) : "memory");
}
// word index of h pair (b, kw) in g_htf  (kw = k/2, 0..511)
__device__ __forceinline__ int widx(int b, int kw) {
    return (kw >> 5) * 2048 + b * 32 + ((kw & 31) ^ ((b & 7) << 2));
}

// ---------------- input projection GEMM (fp16, BK=64, stride 36) ------------
__global__ __launch_bounds__(256) void gemm_gi_kernel(
    const float* __restrict__ x, const float* __restrict__ w_ih,
    const float* __restrict__ b_ih, int l)
{
    const int d = blockIdx.z;
    const float* A    = (l == 0) ? x : g_buf[l - 1];
    const float* W    = w_ih + (size_t)(l * 2 + d) * G3 * I_;
    const float* bias = b_ih + (l * 2 + d) * G3;
    float* C = g_gi[d];

    __shared__ unsigned As[128 * 36];
    __shared__ unsigned Bs[128 * 36];

    const int tid  = threadIdx.x;
    const int lane = tid & 31, warp = tid >> 5;
    const int wm = (warp & 1) * 64, wn = (warp >> 1) * 32;
    const int m0 = blockIdx.y * 128, n0 = blockIdx.x * 128;
    const int g8 = lane >> 2, tg = lane & 3;

    float acc[4][4][4];
    #pragma unroll
    for (int a = 0; a < 4; a++)
        #pragma unroll
        for (int b = 0; b < 4; b++)
            #pragma unroll
            for (int i = 0; i < 4; i++) acc[a][b][i] = 0.f;

    for (int kt = 0; kt < I_; kt += 64) {
        #pragma unroll
        for (int i = 0; i < 8; i++) {            // A tile 128x64 f32 -> h2
            int idx = tid + 256 * i;
            int row = idx >> 4, c4 = (idx & 15) * 4, wc = (idx & 15) * 2;
            float4 v = *reinterpret_cast<const float4*>(
                &A[(size_t)(m0 + row) * I_ + kt + c4]);
            uint2 u = make_uint2(f2h2(v.x, v.y), f2h2(v.z, v.w));
            *reinterpret_cast<uint2*>(&As[row * 36 + wc]) = u;
        }
        #pragma unroll
        for (int i = 0; i < 8; i++) {            // B tile 128x64 (W rows)
            int idx = tid + 256 * i;
            int row = idx >> 4, c4 = (idx & 15) * 4, wc = (idx & 15) * 2;
            float4 v = *reinterpret_cast<const float4*>(
                &W[(size_t)(n0 + row) * I_ + kt + c4]);
            uint2 u = make_uint2(f2h2(v.x, v.y), f2h2(v.z, v.w));
            *reinterpret_cast<uint2*>(&Bs[row * 36 + wc]) = u;
        }
        __syncthreads();
        #pragma unroll
        for (int kk2 = 0; kk2 < 32; kk2 += 8) {  // four k16 mma steps
            unsigned af[4][4], bf[4][2];
            #pragma unroll
            for (int mt = 0; mt < 4; mt++) {
                int r = wm + mt * 16 + g8;
                af[mt][0] = As[r * 36 + kk2 + tg];
                af[mt][1] = As[(r + 8) * 36 + kk2 + tg];
                af[mt][2] = As[r * 36 + kk2 + tg + 4];
                af[mt][3] = As[(r + 8) * 36 + kk2 + tg + 4];
            }
            #pragma unroll
            for (int nt = 0; nt < 4; nt++) {
                int r = wn + nt * 8 + g8;
                bf[nt][0] = Bs[r * 36 + kk2 + tg];
                bf[nt][1] = Bs[r * 36 + kk2 + tg + 4];
            }
            #pragma unroll
            for (int mt = 0; mt < 4; mt++)
                #pragma unroll
                for (int nt = 0; nt < 4; nt++)
                    mmah(acc[mt][nt], af[mt], bf[nt]);
        }
        __syncthreads();
    }
    #pragma unroll
    for (int mt = 0; mt < 4; mt++)
        #pragma unroll
        for (int nt = 0; nt < 4; nt++)
            #pragma unroll
            for (int i = 0; i < 4; i++) {
                int row = m0 + wm + mt * 16 + g8 + 8 * (i >> 1);
                int col = n0 + wn + nt * 8 + 2 * tg + (i & 1);
                C[(size_t)row * G3 + col] = acc[mt][nt][i] + __ldg(&bias[col]);
            }
}

// ---------------- h0 init & flag reset --------------------------------------
__global__ void init_h_kernel(const float* __restrict__ h0, int l)
{
    int i = blockIdx.x * blockDim.x + threadIdx.x;
    if (i < 2 * B_ * H_ / 2) {
        int dir = i >> 15, w = i & 32767;
        int b = w >> 9, kw = w & 511;
        const float* p = &h0[(size_t)(2 * l + dir) * B_ * H_ + (size_t)b * H_ + 2 * kw];
        g_htf[0][dir][widx(b, kw)] = f2h2(p[0], p[1]);
    }
    if (i < 32) g_cflag[i >> 4][i & 15] = 4u;   // h0 counts as step-0 data
    if (i < 2)  g_done[i] = 0u;
}

// ---------------- persistent recurrent kernel -------------------------------
// 128 CTAs (1/SM), 544 threads: 16 compute warps (ks x jh x rb) + 1 control.
// Control warp is EXCLUDED from epilogue barriers (bar.sync 1,512) so it can
// run TMA issue ahead into the next step, hiding TMA head latency behind the
// epilogue. 2 partial barriers/step; release-atomics replace threadfence.
extern __shared__ unsigned smem_dyn[];

__global__ __launch_bounds__(544, 1) void gru_persistent_kernel(
    const float* __restrict__ w_hh, const float* __restrict__ b_hh,
    const float* __restrict__ h0, float* __restrict__ d_out, int l)
{
    const int cta = blockIdx.x;
    const int dir = cta >> 6;
    const int j0  = (cta & 63) * 16;
    const int cj  = (cta & 63) >> 2;         // chunk this CTA co-produces
    const float* Wg = w_hh + (size_t)(l * 2 + dir) * G3 * H_;
    const float* bh = b_hh + (l * 2 + dir) * G3;
    float* y = (l == 2) ? d_out : g_buf[l];

    unsigned* Ws = smem_dyn;                 // 48*512 words, swizzled
    unsigned* Hb = smem_dyn + WS_WORDS;      // 8 x 2048-word TMA ring
    float* red = reinterpret_cast<float*>(smem_dyn + RED_OFF);
    const unsigned hb_u32 = (unsigned)__cvta_generic_to_shared(Hb);
    const unsigned mb_full  = (unsigned)__cvta_generic_to_shared(smem_dyn + MBAR_W);
    const unsigned mb_empty = mb_full + NSLOT * 8;

    const int tid  = threadIdx.x;
    const int lane = tid & 31, warp = tid >> 5;
    const int ks = (warp < 16) ? (warp >> 3) : 0;    // K half
    const int rb = (warp & 3) * 16;          // B rows of this warp
    const int jh = (warp >> 2) & 1;          // j half (0,1)
    const int gq = lane >> 2, tg = lane & 3;
    const unsigned swz = (unsigned)(gq << 2);
    const int kclo = ks * 16;                // word base within chunk's 32

    // ---- load W once: row=gate*16+jj, word(row,wc)=row*512+(wc^((row&7)<<2))
    if (tid < 512) {
        #pragma unroll 4
        for (int i = 0; i < 24; i++) {
            int idx = tid + 512 * i;         // 12288 float4 granules
            int row = idx >> 8, c4 = (idx & 255) * 4, wc = (idx & 255) * 2;
            int g = row >> 4, jj = row & 15;
            float4 v = *reinterpret_cast<const float4*>(
                &Wg[(size_t)(g * H_ + j0 + jj) * H_ + c4]);
            uint2 u = make_uint2(f2h2(v.x, v.y), f2h2(v.z, v.w));
            *reinterpret_cast<uint2*>(
                &Ws[row * 512 + (wc ^ ((row & 7) << 2))]) = u;
        }
    }

    // ---- bias & initial h_prev registers (ks==0 warps) ----
    const int jA = j0 + jh * 8 + 2 * tg;
    float bhv[3][2], hpv[4];
    if (warp < 16 && ks == 0) {
        #pragma unroll
        for (int g = 0; g < 3; g++) {
            bhv[g][0] = __ldg(&bh[g * H_ + jA]);
            bhv[g][1] = __ldg(&bh[g * H_ + jA + 1]);
        }
        #pragma unroll
        for (int i = 0; i < 4; i++) {
            int b = rb + gq + 8 * (i >> 1);
            hpv[i] = __ldg(&h0[(size_t)(2 * l + dir) * B_ * H_
                               + (size_t)b * H_ + jA + (i & 1)]);
        }
    }

    // ---- mbarriers: full cnt 1 (tx), empty cnt 16 ----
    if (tid == 0) {
        #pragma unroll
        for (int m = 0; m < NSLOT; m++) {
            asm volatile("mbarrier.init.shared.b64 [%0], 1;"
                         :: "r"(mb_full + m * 8) : "memory");
            asm volatile("mbarrier.init.shared.b64 [%0], 16;"
                         :: "r"(mb_empty + m * 8) : "memory");
        }
        asm volatile("fence.proxy.async.shared::cta;" ::: "memory");
    }
    __syncthreads();                         // full-CTA: W + mbars ready

    if (warp == 16) {
        // ================= control warp: free-running TMA issuer =========
        if (lane == 0) {
            unsigned euse[NSLOT] = {0};
            for (int s = 0; s < T_; s++) {
                const unsigned* src = g_htf[s & 1][dir];
                const unsigned tgt = 4u * (unsigned)(s + 1);
                for (int c = 0; c < 16; c++) {
                    int slot = (s * 16 + c) & (NSLOT - 1);
                    if (euse[slot] > 0)
                        mbar_wait(mb_empty + slot * 8, (euse[slot] - 1) & 1);
                    euse[slot]++;
                    while (ldacq(&g_cflag[dir][c]) < tgt) __nanosleep(20);
                    unsigned fm = mb_full + slot * 8;
                    asm volatile("mbarrier.arrive.expect_tx.shared.b64 _, [%0], %1;"
                                 :: "r"(fm), "r"(8192u) : "memory");
                    asm volatile(
                        "cp.async.bulk.shared::cta.global.mbarrier::complete_tx::bytes "
                        "[%0], [%1], %2, [%3];"
                        :: "r"(hb_u32 + slot * (HB_SLOT_W * 4)),
                           "l"(src + c * HB_SLOT_W), "r"(8192u), "r"(fm) : "memory");
                }
            }
        }
    } else {
        // ================= compute warps =================================
        unsigned fuse[NSLOT] = {0};
        for (int s = 0; s < T_; s++) {
            const int t = dir ? (T_ - 1 - s) : s;
            unsigned* dstg = g_htf[(s + 1) & 1][dir];

            float acc[3][4];
            #pragma unroll
            for (int g = 0; g < 3; g++)
                #pragma unroll
                for (int i = 0; i < 4; i++) acc[g][i] = 0.f;

            float giv[3][4];
            if (ks == 0) {                   // gi prefetch overlaps GEMM
                #pragma unroll
                for (int i = 0; i < 4; i++) {
                    int b = rb + gq + 8 * (i >> 1);
                    int j = jA + (i & 1);
                    const float* gi = g_gi[dir] + (size_t)(t * B_ + b) * G3;
                    giv[0][i] = __ldg(&gi[j]);
                    giv[1][i] = __ldg(&gi[H_ + j]);
                    giv[2][i] = __ldg(&gi[2 * H_ + j]);
                }
            }

            for (int c = 0; c < 16; c++) {
                int slot = (s * 16 + c) & (NSLOT - 1);
                mbar_wait(mb_full + slot * 8, fuse[slot] & 1);
                fuse[slot]++;

                const unsigned* hb = Hb + slot * HB_SLOT_W;
                #pragma unroll
                for (int kk2 = 0; kk2 < 16; kk2 += 8) {
                    const int kc = kclo + kk2;           // word col in chunk
                    unsigned af[4];
                    int r0 = rb + gq;
                    af[0] = hb[r0 * 32       + ((unsigned)(kc + tg)     ^ swz)];
                    af[1] = hb[(r0 + 8) * 32 + ((unsigned)(kc + tg)     ^ swz)];
                    af[2] = hb[r0 * 32       + ((unsigned)(kc + tg + 4) ^ swz)];
                    af[3] = hb[(r0 + 8) * 32 + ((unsigned)(kc + tg + 4) ^ swz)];
                    const int kw = c * 32 + kc;          // global word in W
                    #pragma unroll
                    for (int g = 0; g < 3; g++) {
                        const int wr = g * 16 + jh * 8 + gq;
                        unsigned bf[2];
                        bf[0] = Ws[wr * 512 + ((unsigned)(kw + tg) ^ swz)];
                        bf[1] = Ws[wr * 512 + ((unsigned)(kw + tg + 4) ^ swz)];
                        mmah(acc[g], af, bf);
                    }
                }
                if (lane == 0)
                    asm volatile("mbarrier.arrive.shared.b64 _, [%0];"
                                 :: "r"(mb_empty + slot * 8) : "memory");
            }

            // ---- K-split partials (dedicated region; no pre-sync needed) --
            if (ks == 1) {
                int base = ((warp & 7) * 32 + lane) * 12;
                #pragma unroll
                for (int g = 0; g < 3; g++)
                    #pragma unroll
                    for (int i = 0; i < 4; i++) red[base + g * 4 + i] = acc[g][i];
            }
            if (tid == 0 && s > 0) {         // lagged h-buffer write gate
                const unsigned tgt = 64u * (unsigned)s;
                while (ldacq(&g_done[dir]) < tgt) __nanosleep(20);
            }
            asm volatile("bar.sync 1, 512;" ::: "memory");   // syncA

            if (ks == 0) {
                int base = (warp * 32 + lane) * 12;
                #pragma unroll
                for (int g = 0; g < 3; g++)
                    #pragma unroll
                    for (int i = 0; i < 4; i++) acc[g][i] += red[base + g * 4 + i];

                #pragma unroll
                for (int i = 0; i < 4; i++) {
                    float r = 1.f / (1.f + expf(-(giv[0][i] + acc[0][i] + bhv[0][i & 1])));
                    float z = 1.f / (1.f + expf(-(giv[1][i] + acc[1][i] + bhv[1][i & 1])));
                    float n = tanhf(giv[2][i] + r * (acc[2][i] + bhv[2][i & 1]));
                    hpv[i] = (1.f - z) * n + z * hpv[i];
                }
                const int kw = jA >> 1;
                #pragma unroll
                for (int p = 0; p < 2; p++) {
                    int b = rb + gq + 8 * p;
                    __stcg(&dstg[widx(b, kw)], f2h2(hpv[2 * p], hpv[2 * p + 1]));
                }
            }
            asm volatile("bar.sync 1, 512;" ::: "memory");   // syncB

            if (tid == 0) {
                red_release(&g_cflag[dir][cj]);   // release orders h stores
                red_release(&g_done[dir]);
            }
            if (ks == 0) {                   // y stores off the critical path
                #pragma unroll
                for (int p = 0; p < 2; p++) {
                    int b = rb + gq + 8 * p;
                    float2 v = make_float2(hpv[2 * p], hpv[2 * p + 1]);
                    *reinterpret_cast<float2*>(
                        &y[(size_t)(t * B_ + b) * 2048 + dir * H_ + jA]) = v;
                }
            }
        }
    }
}

// ---------------- launch ------------------------------------------------------
extern "C" void kernel_launch(void* const* d_in, const int* in_sizes, int n_in,
                              void* d_out, int out_size)
{
    const float* x    = (const float*)d_in[0];
    const float* h0   = (const float*)d_in[1];
    const float* w_ih = (const float*)d_in[2];
    const float* w_hh = (const float*)d_in[3];
    const float* b_ih = (const float*)d_in[4];
    const float* b_hh = (const float*)d_in[5];
    float* out = (float*)d_out;

    cudaFuncSetAttribute(gru_persistent_kernel,
                         cudaFuncAttributeMaxDynamicSharedMemorySize, SMEM_STEP);

    for (int l = 0; l < 3; l++) {
        dim3 gg(G3 / 128, TB / 128, 2);
        gemm_gi_kernel<<<gg, 256>>>(x, w_ih, b_ih, l);
        init_h_kernel<<<(2 * B_ * H_ / 2 + 255) / 256, 256>>>(h0, l);
        gru_persistent_kernel<<<128, 544, SMEM_STEP>>>(w_hh, b_hh, h0, out, l);
    }
}

// round 14
// speedup vs baseline: 1.1292x; 1.1292x over previous
#include <cuda_runtime.h>
#include <cuda_fp16.h>

#define T_  256
#define B_  64
#define H_  1024
#define G3  3072
#define I_  2048
#define TB  16384   // T_*B_

#define NSLOT      3
#define NCHUNK     4                         // big chunks per step
// smem words: Ws[48*512] | Hb[3][8192] | red[3072] | mbar[32]
#define WS_WORDS   (48 * 512)                // W: 96KB fp16
#define HB_SLOT_W  8192                      // one 64x256 fp16 chunk (32KB)
#define RED_OFF    (WS_WORDS + NSLOT * HB_SLOT_W)
#define RED_WORDS  3072
#define MBAR_W     (RED_OFF + RED_WORDS)
#define SMEM_STEP  ((MBAR_W + 32) * 4)       // ~205KB (1 CTA/SM)

// ---------------- scratch ----------------------------------------------------
__device__ float g_gi[2][(size_t)TB * G3];
__device__ float g_buf[2][(size_t)TB * I_];
// h: fp16 pairs; layout identical to R12 (16 sub-blocks of [64][32] words);
// big chunk c = sub-blocks 4c..4c+3 (contiguous 8192 words).
// word(b,kw) = (kw>>5)*2048 + b*32 + ((kw&31) ^ ((b&7)<<2))
__device__ __align__(1024) unsigned g_htf[2][2][B_ * H_ / 2];
__device__ unsigned g_cflag[2][NCHUNK];      // per-(dir,bigchunk) producer counts
__device__ unsigned g_done[2];               // per-dir completed-read counter

// ---------------- helpers ---------------------------------------------------
__device__ __forceinline__ unsigned f2h2(float lo, float hi) {
    unsigned u;                              // pack: lower=lo, upper=hi
    asm("cvt.rn.f16x2.f32 %0, %1, %2;" : "=r"(u) : "f"(hi), "f"(lo));
    return u;
}
__device__ __forceinline__ void mmah(float* c, const unsigned* a, const unsigned* b) {
    asm volatile(
        "mma.sync.aligned.m16n8k16.row.col.f32.f16.f16.f32 "
        "{%0,%1,%2,%3}, {%4,%5,%6,%7}, {%8,%9}, {%0,%1,%2,%3};"
        : "+f"(c[0]), "+f"(c[1]), "+f"(c[2]), "+f"(c[3])
        : "r"(a[0]), "r"(a[1]), "r"(a[2]), "r"(a[3]), "r"(b[0]), "r"(b[1]));
}
__device__ __forceinline__ void mbar_wait(unsigned mb, unsigned par) {
    asm volatile(
        "{\n\t.reg .pred P;\nW_%=:\n\t"
        "mbarrier.try_wait.parity.shared::cta.b64 P, [%0], %1;\n\t"
        "@!P bra W_%=;\n\t}" :: "r"(mb), "r"(par) : "memory");
}
__device__ __forceinline__ unsigned ldacq(const unsigned* p) {
    unsigned v;
    asm volatile("ld.acquire.gpu.global.u32 %0, [%1];" : "=r"(v) : "l"(p) : "memory");
    return v;
}
// word index of h pair (b, kw) in g_htf  (kw = k/2, 0..511)
__device__ __forceinline__ int widx(int b, int kw) {
    return (kw >> 5) * 2048 + b * 32 + ((kw & 31) ^ ((b & 7) << 2));
}

// ---------------- input projection GEMM (R12 version, fp16 BK=32) -----------
__global__ __launch_bounds__(256) void gemm_gi_kernel(
    const float* __restrict__ x, const float* __restrict__ w_ih,
    const float* __restrict__ b_ih, int l)
{
    const int d = blockIdx.z;
    const float* A    = (l == 0) ? x : g_buf[l - 1];
    const float* W    = w_ih + (size_t)(l * 2 + d) * G3 * I_;
    const float* bias = b_ih + (l * 2 + d) * G3;
    float* C = g_gi[d];

    __shared__ unsigned As[128 * 20];
    __shared__ unsigned Bs[128 * 20];

    const int tid  = threadIdx.x;
    const int lane = tid & 31, warp = tid >> 5;
    const int wm = (warp & 1) * 64, wn = (warp >> 1) * 32;
    const int m0 = blockIdx.y * 128, n0 = blockIdx.x * 128;
    const int g8 = lane >> 2, tg = lane & 3;

    float acc[4][4][4];
    #pragma unroll
    for (int a = 0; a < 4; a++)
        #pragma unroll
        for (int b = 0; b < 4; b++)
            #pragma unroll
            for (int i = 0; i < 4; i++) acc[a][b][i] = 0.f;

    for (int kt = 0; kt < I_; kt += 32) {
        #pragma unroll
        for (int i = 0; i < 4; i++) {            // A tile 128x32 f32 -> h2
            int idx = tid + 256 * i;
            int row = idx >> 3, c4 = (idx & 7) * 4, wc = (idx & 7) * 2;
            float4 v = *reinterpret_cast<const float4*>(
                &A[(size_t)(m0 + row) * I_ + kt + c4]);
            uint2 u = make_uint2(f2h2(v.x, v.y), f2h2(v.z, v.w));
            *reinterpret_cast<uint2*>(&As[row * 20 + wc]) = u;
        }
        #pragma unroll
        for (int i = 0; i < 4; i++) {            // B tile 128x32 (W rows)
            int idx = tid + 256 * i;
            int row = idx >> 3, c4 = (idx & 7) * 4, wc = (idx & 7) * 2;
            float4 v = *reinterpret_cast<const float4*>(
                &W[(size_t)(n0 + row) * I_ + kt + c4]);
            uint2 u = make_uint2(f2h2(v.x, v.y), f2h2(v.z, v.w));
            *reinterpret_cast<uint2*>(&Bs[row * 20 + wc]) = u;
        }
        __syncthreads();
        #pragma unroll
        for (int kk2 = 0; kk2 < 16; kk2 += 8) {  // two k16 mma steps
            unsigned af[4][4], bf[4][2];
            #pragma unroll
            for (int mt = 0; mt < 4; mt++) {
                int r = wm + mt * 16 + g8;
                af[mt][0] = As[r * 20 + kk2 + tg];
                af[mt][1] = As[(r + 8) * 20 + kk2 + tg];
                af[mt][2] = As[r * 20 + kk2 + tg + 4];
                af[mt][3] = As[(r + 8) * 20 + kk2 + tg + 4];
            }
            #pragma unroll
            for (int nt = 0; nt < 4; nt++) {
                int r = wn + nt * 8 + g8;
                bf[nt][0] = Bs[r * 20 + kk2 + tg];
                bf[nt][1] = Bs[r * 20 + kk2 + tg + 4];
            }
            #pragma unroll
            for (int mt = 0; mt < 4; mt++)
                #pragma unroll
                for (int nt = 0; nt < 4; nt++)
                    mmah(acc[mt][nt], af[mt], bf[nt]);
        }
        __syncthreads();
    }
    #pragma unroll
    for (int mt = 0; mt < 4; mt++)
        #pragma unroll
        for (int nt = 0; nt < 4; nt++)
            #pragma unroll
            for (int i = 0; i < 4; i++) {
                int row = m0 + wm + mt * 16 + g8 + 8 * (i >> 1);
                int col = n0 + wn + nt * 8 + 2 * tg + (i & 1);
                C[(size_t)row * G3 + col] = acc[mt][nt][i] + __ldg(&bias[col]);
            }
}

// ---------------- h0 init & flag reset --------------------------------------
__global__ void init_h_kernel(const float* __restrict__ h0, int l)
{
    int i = blockIdx.x * blockDim.x + threadIdx.x;
    if (i < 2 * B_ * H_ / 2) {
        int dir = i >> 15, w = i & 32767;
        int b = w >> 9, kw = w & 511;
        const float* p = &h0[(size_t)(2 * l + dir) * B_ * H_ + (size_t)b * H_ + 2 * kw];
        g_htf[0][dir][widx(b, kw)] = f2h2(p[0], p[1]);
    }
    if (i < 2 * NCHUNK) g_cflag[i >> 2][i & 3] = 16u;  // h0 = step-0 data
    if (i < 2)  g_done[i] = 0u;
}

// ---------------- persistent recurrent kernel (32KB chunks, 3-slot ring) ----
// 128 CTAs (1/SM), 544 threads: 16 compute warps (ks x jh x rb) + 1 control.
// Same structure as R12; only granularity changed: 4 x 32KB chunks per step
// (protocol ops / TMA count / flag polls all divided by 4).
extern __shared__ unsigned smem_dyn[];

__global__ __launch_bounds__(544, 1) void gru_persistent_kernel(
    const float* __restrict__ w_hh, const float* __restrict__ b_hh,
    const float* __restrict__ h0, float* __restrict__ d_out, int l)
{
    const int cta = blockIdx.x;
    const int dir = cta >> 6;
    const int j0  = (cta & 63) * 16;
    const int cj  = (cta & 63) >> 4;         // big chunk this CTA co-produces
    const float* Wg = w_hh + (size_t)(l * 2 + dir) * G3 * H_;
    const float* bh = b_hh + (l * 2 + dir) * G3;
    float* y = (l == 2) ? d_out : g_buf[l];

    unsigned* Ws = smem_dyn;                 // 48*512 words, swizzled
    unsigned* Hb = smem_dyn + WS_WORDS;      // 3 x 8192-word TMA ring
    float* red = reinterpret_cast<float*>(smem_dyn + RED_OFF);
    const unsigned hb_u32 = (unsigned)__cvta_generic_to_shared(Hb);
    const unsigned mb_full  = (unsigned)__cvta_generic_to_shared(smem_dyn + MBAR_W);
    const unsigned mb_empty = mb_full + NSLOT * 8;

    const int tid  = threadIdx.x;
    const int lane = tid & 31, warp = tid >> 5;
    const int ks = (warp < 16) ? (warp >> 3) : 0;    // K half
    const int rb = (warp & 3) * 16;          // B rows of this warp
    const int jh = (warp >> 2) & 1;          // j half (0,1)
    const int gq = lane >> 2, tg = lane & 3;
    const unsigned swz = (unsigned)(gq << 2);
    const int kclo = ks * 16;                // word base within sub-block's 32

    // ---- load W once: row=gate*16+jj, word(row,wc)=row*512+(wc^((row&7)<<2))
    if (tid < 512) {
        #pragma unroll 4
        for (int i = 0; i < 24; i++) {
            int idx = tid + 512 * i;         // 12288 float4 granules
            int row = idx >> 8, c4 = (idx & 255) * 4, wc = (idx & 255) * 2;
            int g = row >> 4, jj = row & 15;
            float4 v = *reinterpret_cast<const float4*>(
                &Wg[(size_t)(g * H_ + j0 + jj) * H_ + c4]);
            uint2 u = make_uint2(f2h2(v.x, v.y), f2h2(v.z, v.w));
            *reinterpret_cast<uint2*>(
                &Ws[row * 512 + (wc ^ ((row & 7) << 2))]) = u;
        }
    }

    // ---- bias & initial h_prev registers (ks==0 warps) ----
    const int jA = j0 + jh * 8 + 2 * tg;
    float bhv[3][2], hpv[4];
    if (warp < 16 && ks == 0) {
        #pragma unroll
        for (int g = 0; g < 3; g++) {
            bhv[g][0] = __ldg(&bh[g * H_ + jA]);
            bhv[g][1] = __ldg(&bh[g * H_ + jA + 1]);
        }
        #pragma unroll
        for (int i = 0; i < 4; i++) {
            int b = rb + gq + 8 * (i >> 1);
            hpv[i] = __ldg(&h0[(size_t)(2 * l + dir) * B_ * H_
                               + (size_t)b * H_ + jA + (i & 1)]);
        }
    }

    // ---- mbarriers: full cnt 1 (tx), empty cnt 16 ----
    if (tid == 0) {
        #pragma unroll
        for (int m = 0; m < NSLOT; m++) {
            asm volatile("mbarrier.init.shared.b64 [%0], 1;"
                         :: "r"(mb_full + m * 8) : "memory");
            asm volatile("mbarrier.init.shared.b64 [%0], 16;"
                         :: "r"(mb_empty + m * 8) : "memory");
        }
        asm volatile("fence.proxy.async.shared::cta;" ::: "memory");
    }
    __syncthreads();

    unsigned fuse[NSLOT] = {0}, euse[NSLOT] = {0};
    int fsl = 0, esl = 0;                    // running slot counters (mod 3)

    for (int s = 0; s < T_; s++) {
        const int t = dir ? (T_ - 1 - s) : s;
        const unsigned* src = g_htf[s & 1][dir];
        unsigned* dstg = g_htf[(s + 1) & 1][dir];

        if (warp == 16 && lane == 0) {
            // -------- control: issue 4 big-chunk TMAs ---------------------
            const unsigned tgt = 16u * (unsigned)(s + 1);
            for (int c = 0; c < NCHUNK; c++) {
                int slot = esl; if (++esl == NSLOT) esl = 0;
                if (euse[slot] > 0)
                    mbar_wait(mb_empty + slot * 8, (euse[slot] - 1) & 1);
                euse[slot]++;
                while (ldacq(&g_cflag[dir][c]) < tgt) __nanosleep(20);
                unsigned fm = mb_full + slot * 8;
                asm volatile("mbarrier.arrive.expect_tx.shared.b64 _, [%0], %1;"
                             :: "r"(fm), "r"(32768u) : "memory");
                asm volatile(
                    "cp.async.bulk.shared::cta.global.mbarrier::complete_tx::bytes "
                    "[%0], [%1], %2, [%3];"
                    :: "r"(hb_u32 + slot * (HB_SLOT_W * 4)),
                       "l"(src + c * HB_SLOT_W), "r"(32768u), "r"(fm) : "memory");
            }
        }

        float acc[3][4];
        #pragma unroll
        for (int g = 0; g < 3; g++)
            #pragma unroll
            for (int i = 0; i < 4; i++) acc[g][i] = 0.f;

        float giv[3][4];
        if (warp < 16 && ks == 0) {          // gi prefetch overlaps GEMM
            #pragma unroll
            for (int i = 0; i < 4; i++) {
                int b = rb + gq + 8 * (i >> 1);
                int j = jA + (i & 1);
                const float* gi = g_gi[dir] + (size_t)(t * B_ + b) * G3;
                giv[0][i] = __ldg(&gi[j]);
                giv[1][i] = __ldg(&gi[H_ + j]);
                giv[2][i] = __ldg(&gi[2 * H_ + j]);
            }
        }

        if (warp < 16) {
            // -------- compute warps: consume 4 big chunks -----------------
            for (int c = 0; c < NCHUNK; c++) {
                int slot = fsl; if (++fsl == NSLOT) fsl = 0;
                mbar_wait(mb_full + slot * 8, fuse[slot] & 1);
                fuse[slot]++;

                #pragma unroll
                for (int sub = 0; sub < 4; sub++) {
                    const unsigned* hb = Hb + slot * HB_SLOT_W + sub * 2048;
                    #pragma unroll
                    for (int kk2 = 0; kk2 < 16; kk2 += 8) {
                        const int kc = kclo + kk2;       // word col in sub
                        unsigned af[4];
                        int r0 = rb + gq;
                        af[0] = hb[r0 * 32       + ((unsigned)(kc + tg)     ^ swz)];
                        af[1] = hb[(r0 + 8) * 32 + ((unsigned)(kc + tg)     ^ swz)];
                        af[2] = hb[r0 * 32       + ((unsigned)(kc + tg + 4) ^ swz)];
                        af[3] = hb[(r0 + 8) * 32 + ((unsigned)(kc + tg + 4) ^ swz)];
                        const int kw = (c * 4 + sub) * 32 + kc;  // word in W
                        #pragma unroll
                        for (int g = 0; g < 3; g++) {
                            const int wr = g * 16 + jh * 8 + gq;
                            unsigned bf[2];
                            bf[0] = Ws[wr * 512 + ((unsigned)(kw + tg) ^ swz)];
                            bf[1] = Ws[wr * 512 + ((unsigned)(kw + tg + 4) ^ swz)];
                            mmah(acc[g], af, bf);
                        }
                    }
                }
                if (lane == 0)
                    asm volatile("mbarrier.arrive.shared.b64 _, [%0];"
                                 :: "r"(mb_empty + slot * 8) : "memory");
            }
        }

        __syncthreads();                     // sync1: all chunks consumed

        // ---- K-split partials into dedicated red region ----
        if (warp < 16 && ks == 1) {
            int base = ((warp & 7) * 32 + lane) * 12;
            #pragma unroll
            for (int g = 0; g < 3; g++)
                #pragma unroll
                for (int i = 0; i < 4; i++) red[base + g * 4 + i] = acc[g][i];
        }
        if (tid == 0 && s > 0) {             // lagged h-buffer write gate
            const unsigned tgt = 64u * (unsigned)s;
            while (ldacq(&g_done[dir]) < tgt) __nanosleep(20);
        }
        __syncthreads();                     // sync2

        if (warp < 16 && ks == 0) {
            int base = (warp * 32 + lane) * 12;
            #pragma unroll
            for (int g = 0; g < 3; g++)
                #pragma unroll
                for (int i = 0; i < 4; i++) acc[g][i] += red[base + g * 4 + i];

            #pragma unroll
            for (int i = 0; i < 4; i++) {
                float r = 1.f / (1.f + expf(-(giv[0][i] + acc[0][i] + bhv[0][i & 1])));
                float z = 1.f / (1.f + expf(-(giv[1][i] + acc[1][i] + bhv[1][i & 1])));
                float n = tanhf(giv[2][i] + r * (acc[2][i] + bhv[2][i & 1]));
                hpv[i] = (1.f - z) * n + z * hpv[i];
            }
            // h store: one half2 word per b (pairs i=0,1 and i=2,3)
            const int kw = jA >> 1;
            #pragma unroll
            for (int p = 0; p < 2; p++) {
                int b = rb + gq + 8 * p;
                __stcg(&dstg[widx(b, kw)], f2h2(hpv[2 * p], hpv[2 * p + 1]));
            }
        }
        __syncthreads();                     // sync3: h stores done CTA-wide

        if (tid == 0) {
            __threadfence();                 // cumulative release of h stores
            atomicAdd(&g_cflag[dir][cj], 1u);
            atomicAdd(&g_done[dir], 1u);
        }
        if (warp < 16 && ks == 0) {          // y stores off the critical path
            #pragma unroll
            for (int p = 0; p < 2; p++) {
                int b = rb + gq + 8 * p;
                float2 v = make_float2(hpv[2 * p], hpv[2 * p + 1]);
                *reinterpret_cast<float2*>(
                    &y[(size_t)(t * B_ + b) * 2048 + dir * H_ + jA]) = v;
            }
        }
    }
}

// ---------------- launch ------------------------------------------------------
extern "C" void kernel_launch(void* const* d_in, const int* in_sizes, int n_in,
                              void* d_out, int out_size)
{
    const float* x    = (const float*)d_in[0];
    const float* h0   = (const float*)d_in[1];
    const float* w_ih = (const float*)d_in[2];
    const float* w_hh = (const float*)d_in[3];
    const float* b_ih = (const float*)d_in[4];
    const float* b_hh = (const float*)d_in[5];
    float* out = (float*)d_out;

    cudaFuncSetAttribute(gru_persistent_kernel,
                         cudaFuncAttributeMaxDynamicSharedMemorySize, SMEM_STEP);

    for (int l = 0; l < 3; l++) {
        dim3 gg(G3 / 128, TB / 128, 2);
        gemm_gi_kernel<<<gg, 256>>>(x, w_ih, b_ih, l);
        init_h_kernel<<<(2 * B_ * H_ / 2 + 255) / 256, 256>>>(h0, l);
        gru_persistent_kernel<<<128, 544, SMEM_STEP>>>(w_hh, b_hh, h0, out, l);
    }
}